// round 15
// baseline (speedup 1.0000x reference)
#include <cuda_runtime.h>
#include <cstdint>
#include <cstddef>

#define T_LEN 512
#define BATCH 64
#define ISZ   256
#define HID   512
#define NCOL  2048      // 4*HID
#define GRID2 128       // 4 groups x 32 CTAs

// ---------------- device scratch ----------------
__device__ float g_gx[(size_t)T_LEN * NCOL * BATCH];   // [T][2048][64], bx+bh folded in
__device__ float g_h[2][BATCH * HID];                  // h double buffer
__device__ unsigned g_done[GRID2];                     // per-block step counters (MONOTONIC)
__device__ unsigned gx_ready[T_LEN];                   // per-t tile counters (MONOTONIC, 64/t/replay)

// ---------------- packed fp32x2 FMA ----------------
__device__ __forceinline__ unsigned long long fma2(unsigned long long a,
                                                   unsigned long long b,
                                                   unsigned long long c) {
    unsigned long long d;
    asm("fma.rn.f32x2 %0, %1, %2, %3;" : "=l"(d) : "l"(a), "l"(b), "l"(c));
    return d;
}
__device__ __forceinline__ float hsum2(unsigned long long v) {
    float lo, hi;
    asm("mov.b64 {%0,%1}, %2;" : "=f"(lo), "=f"(hi) : "l"(v));
    return lo + hi;
}
__device__ __forceinline__ float sigf(float x) {
    return 1.0f / (1.0f + __expf(-x));
}
__device__ __forceinline__ float tanh_acc(float x) {
    float ax = fabsf(x);
    float e  = __expf(-2.0f * ax);
    float r  = (1.0f - e) / (1.0f + e);
    return copysignf(r, x);
}

// =====================================================================
// Phase 1 (small co-resident tiles): gx[t][n][b] = x[t,b,:]·Wx[n,:] + bias
//   grid (64, 512), 128 threads, tile 32n x 64b x 256k, smem 50.7KB,
//   <=102 regs -> co-resides with a phase-2 CTA on the same SM.
//   Releases gx_ready[t] (+1 per tile, 64 tiles per t).
// =====================================================================
#define P1_PAD 132

extern "C" __global__ void __launch_bounds__(128, 5)
lstm_phase1(const float* __restrict__ x, const float* __restrict__ Wx,
            const float* __restrict__ bx, const float* __restrict__ bh)
{
    extern __shared__ float smem[];
    float* xs   = smem;                    // [64][132]
    float* ws1  = smem + 64 * P1_PAD;      // [32][132]
    float* sbuf = smem;                    // alias xs: [32][68]

    const int t   = blockIdx.y;
    const int n0  = blockIdx.x * 32;
    const int tid = threadIdx.x;
    const int nq  = tid & 7;               // 0..7
    const int bq  = tid >> 3;              // 0..15

    unsigned long long acc[4][4];          // [r: n-block][s: b-block]
    #pragma unroll
    for (int r = 0; r < 4; r++)
        #pragma unroll
        for (int s = 0; s < 4; s++) acc[r][s] = 0ull;

    #pragma unroll
    for (int ks2 = 0; ks2 < 2; ks2++) {
        const int k0 = ks2 * 128;
        __syncthreads();
        for (int e = tid; e < 64 * 32; e += 128) {
            int bb = e >> 5, kq = e & 31;
            float4 v = *reinterpret_cast<const float4*>(
                &x[((size_t)t * BATCH + bb) * ISZ + k0 + kq * 4]);
            *reinterpret_cast<float4*>(&xs[bb * P1_PAD + kq * 4]) = v;
        }
        for (int e = tid; e < 32 * 32; e += 128) {
            int rr = e >> 5, kq = e & 31;
            float4 v = *reinterpret_cast<const float4*>(
                &Wx[(size_t)(n0 + rr) * ISZ + k0 + kq * 4]);
            *reinterpret_cast<float4*>(&ws1[rr * P1_PAD + kq * 4]) = v;
        }
        __syncthreads();

        #pragma unroll 4
        for (int k4 = 0; k4 < 128; k4 += 4) {
            ulonglong2 xv[4], wv[4];
            #pragma unroll
            for (int s = 0; s < 4; s++)
                xv[s] = *reinterpret_cast<const ulonglong2*>(
                    &xs[(bq + 16 * s) * P1_PAD + k4]);
            #pragma unroll
            for (int r = 0; r < 4; r++)
                wv[r] = *reinterpret_cast<const ulonglong2*>(
                    &ws1[(nq + 8 * r) * P1_PAD + k4]);
            #pragma unroll
            for (int r = 0; r < 4; r++)
                #pragma unroll
                for (int s = 0; s < 4; s++) {
                    acc[r][s] = fma2(xv[s].x, wv[r].x, acc[r][s]);
                    acc[r][s] = fma2(xv[s].y, wv[r].y, acc[r][s]);
                }
        }
    }
    __syncthreads();

    #pragma unroll
    for (int r = 0; r < 4; r++)
        #pragma unroll
        for (int s = 0; s < 4; s++)
            sbuf[(nq + 8 * r) * 68 + (bq + 16 * s)] = hsum2(acc[r][s]);
    __syncthreads();

    for (int e = tid; e < 32 * 16; e += 128) {
        int row = e >> 4, c4 = e & 15;
        int n = n0 + row;
        float bias = bx[n] + bh[n];
        float4 v = *reinterpret_cast<float4*>(&sbuf[row * 68 + c4 * 4]);
        v.x += bias; v.y += bias; v.z += bias; v.w += bias;
        *reinterpret_cast<float4*>(
            &g_gx[((size_t)t * NCOL + n) * BATCH + c4 * 4]) = v;
    }
    __syncthreads();     // all stores issued block-wide
    if (tid == 0) {
        __threadfence();
        asm volatile("red.release.gpu.global.add.u32 [%0], %1;"
                     :: "l"(&gx_ready[t]), "r"(1u) : "memory");
    }
}

// =====================================================================
// Phase 2: R14-proven recurrence, + monotonic counters + gx gating +
//   red[] aliased onto hs (smem 197KB -> 165KB for co-residency).
// =====================================================================
#define HS_PAD 516
#define WS_PAD 516
#define RED_PAD 9
#define NTHR2  256
#define H_ROW_BYTES (HID * 4)            // 2048
#define H_TILE_BYTES (16 * H_ROW_BYTES)  // 32768
#define RED_BYTES (16 * 16 * RED_PAD * 4 * 4)   // 36864 (>= hs 33024: red zone holds both)

extern "C" __global__ void __launch_bounds__(NTHR2, 1)
lstm_phase2(const float* __restrict__ Wh, float* __restrict__ out)
{
    extern __shared__ float smem[];
    float* hs  = smem;                        // [16][516] (inside red zone)
    float* red = smem;                        // ALIAS: reused after dot each step
    float* ws  = smem + RED_BYTES / 4;        // [64][516] Wh slice
    __shared__ unsigned long long s_mbar;

    const int tid  = threadIdx.x;
    const int bid  = blockIdx.x;
    const int gr   = bid >> 5;              // group 0..3
    const int c    = bid & 31;              // CTA within group
    const int lane = tid & 31;
    const int ks   = tid >> 5;              // k-slice 0..7 (64 k each)
    const int bq   = (tid >> 4) & 1;        // batch parity
    const int u    = tid & 15;              // unit-in-CTA
    const int j    = c * 16 + u;            // global unit
    const int b0   = gr * 16;               // group's first batch
    const int kofs = ks * 64;
    const int bf   = 2 * ks + bq;           // batch this thread finalizes

    uint32_t mbar_addr;
    {
        uint64_t tmp;
        asm("cvta.to.shared.u64 %0, %1;" : "=l"(tmp) : "l"(&s_mbar));
        mbar_addr = (uint32_t)tmp;
    }

    // monotonic bases (own slot is quiescent at kernel entry)
    unsigned base;
    asm volatile("ld.relaxed.gpu.global.u32 %0, [%1];"
                 : "=r"(base) : "l"(&g_done[bid]) : "memory");
    const unsigned gxneed = ((base >> 9) + 1u) << 6;   // 64*(replay+1)

    // Wh slice resident
    for (int e = tid; e < 64 * 128; e += NTHR2) {
        int row = e >> 7, kk = e & 127;
        int g = row >> 4, uu = row & 15;
        float4 v = *reinterpret_cast<const float4*>(
            &Wh[((size_t)(g * HID + c * 16 + uu)) * HID + kk * 4]);
        *reinterpret_cast<float4*>(&ws[row * WS_PAD + kk * 4]) = v;
    }
    if (tid == 0) {
        asm volatile("mbarrier.init.shared.b64 [%0], 1;"
                     :: "r"(mbar_addr) : "memory");
    }
    float c_state = 0.0f;
    unsigned ph = 0;
    __syncthreads();   // ws + mbar ready

    for (int t = 0; t < T_LEN; t++) {
        const int rb = t & 1;
        const int wbuf = rb ^ 1;

        // ---- gx gate: wait until phase1 produced gx[t] (usually instant) ----
        {
            unsigned v;
            asm volatile("ld.acquire.gpu.global.u32 %0, [%1];"
                         : "=r"(v) : "l"(&gx_ready[t]) : "memory");
            while ((int)(v - gxneed) < 0) {
                __nanosleep(32);
                asm volatile("ld.acquire.gpu.global.u32 %0, [%1];"
                             : "=r"(v) : "l"(&gx_ready[t]) : "memory");
            }
        }
        float gxv[4];
        #pragma unroll
        for (int g = 0; g < 4; g++)
            gxv[g] = g_gx[((size_t)t * NCOL + g * HID + j) * BATCH + b0 + bf];

        unsigned long long acc[4][8];
        #pragma unroll
        for (int g = 0; g < 4; g++)
            #pragma unroll
            for (int i = 0; i < 8; i++) acc[g][i] = 0ull;

        if (t > 0) {
            // ---- group barrier wait: this group's 32 slots >= base+t ----
            if (tid < 32) {
                const unsigned need = base + (unsigned)t;
                bool ok;
                do {
                    unsigned v;
                    asm volatile("ld.relaxed.gpu.global.u32 %0, [%1];"
                                 : "=r"(v) : "l"(&g_done[(gr << 5) + lane]) : "memory");
                    ok = __all_sync(0xFFFFFFFFu, (int)(v - need) >= 0);
                    if (!ok) __nanosleep(20);
                } while (!ok);
                asm volatile("fence.acq_rel.gpu;" ::: "memory");
            }
            __syncthreads();   // gated on h(t-1) ready; hs/red WAR-safe

            // ---- bulk-copy 16 h rows (2KB each) via async proxy ----
            if (tid == 0) {
                asm volatile("mbarrier.arrive.expect_tx.shared.b64 _, [%0], %1;"
                             :: "r"(mbar_addr), "r"((unsigned)H_TILE_BYTES)
                             : "memory");
                const float* hsrc = g_h[rb] + (size_t)b0 * HID;
                #pragma unroll
                for (int r = 0; r < 16; r++) {
                    uint32_t dst;
                    {
                        uint64_t tmp;
                        asm("cvta.to.shared.u64 %0, %1;"
                            : "=l"(tmp) : "l"(&hs[r * HS_PAD]));
                        dst = (uint32_t)tmp;
                    }
                    asm volatile(
                        "cp.async.bulk.shared::cta.global.mbarrier::complete_tx::bytes"
                        " [%0], [%1], %2, [%3];"
                        :: "r"(dst), "l"(&hsrc[(size_t)r * HID]),
                           "r"((unsigned)H_ROW_BYTES), "r"(mbar_addr)
                        : "memory");
                }
            }
            {
                unsigned done;
                asm volatile(
                    "{\n\t.reg .pred p;\n\t"
                    "mbarrier.try_wait.parity.shared.b64 p, [%1], %2;\n\t"
                    "selp.b32 %0, 1, 0, p;\n\t}"
                    : "=r"(done) : "r"(mbar_addr), "r"(ph) : "memory");
                while (!done) {
                    asm volatile(
                        "{\n\t.reg .pred p;\n\t"
                        "mbarrier.try_wait.parity.shared.b64 p, [%1], %2;\n\t"
                        "selp.b32 %0, 1, 0, p;\n\t}"
                        : "=r"(done) : "r"(mbar_addr), "r"(ph) : "memory");
                }
            }
            ph ^= 1u;

            // ---- dot: 4 gates x 8 batches (b = bq+2i) over 64 k ----
            const float* wp0 = &ws[(0 * 16 + u) * WS_PAD + kofs];
            const float* wp1 = &ws[(1 * 16 + u) * WS_PAD + kofs];
            const float* wp2 = &ws[(2 * 16 + u) * WS_PAD + kofs];
            const float* wp3 = &ws[(3 * 16 + u) * WS_PAD + kofs];
            const float* hp  = &hs[bq * HS_PAD + kofs];
            #pragma unroll 4
            for (int k4 = 0; k4 < 64; k4 += 4) {
                ulonglong2 w0 = *reinterpret_cast<const ulonglong2*>(&wp0[k4]);
                ulonglong2 w1 = *reinterpret_cast<const ulonglong2*>(&wp1[k4]);
                ulonglong2 w2 = *reinterpret_cast<const ulonglong2*>(&wp2[k4]);
                ulonglong2 w3 = *reinterpret_cast<const ulonglong2*>(&wp3[k4]);
                #pragma unroll
                for (int i = 0; i < 8; i++) {
                    ulonglong2 h2 = *reinterpret_cast<const ulonglong2*>(
                        &hp[(2 * i) * HS_PAD + k4]);
                    acc[0][i] = fma2(h2.x, w0.x, acc[0][i]);
                    acc[0][i] = fma2(h2.y, w0.y, acc[0][i]);
                    acc[1][i] = fma2(h2.x, w1.x, acc[1][i]);
                    acc[1][i] = fma2(h2.y, w1.y, acc[1][i]);
                    acc[2][i] = fma2(h2.x, w2.x, acc[2][i]);
                    acc[2][i] = fma2(h2.y, w2.y, acc[2][i]);
                    acc[3][i] = fma2(h2.x, w3.x, acc[3][i]);
                    acc[3][i] = fma2(h2.y, w3.y, acc[3][i]);
                }
            }
        }

        __syncthreads();   // ALL dots done -> safe to overwrite hs with red partials

        #pragma unroll
        for (int i = 0; i < 8; i++) {
            int b = bq + 2 * i;
            float4 pv = make_float4(hsum2(acc[0][i]), hsum2(acc[1][i]),
                                    hsum2(acc[2][i]), hsum2(acc[3][i]));
            *reinterpret_cast<float4*>(
                &red[((b * 16 + u) * RED_PAD + ks) * 4]) = pv;
        }
        __syncthreads();   // partials visible

        float s0 = 0.f, s1 = 0.f, s2 = 0.f, s3 = 0.f;
        #pragma unroll
        for (int q = 0; q < 8; q++) {
            float4 v = *reinterpret_cast<const float4*>(
                &red[((bf * 16 + u) * RED_PAD + q) * 4]);
            s0 += v.x; s1 += v.y; s2 += v.z; s3 += v.w;
        }
        float f  = sigf(s0 + gxv[0]);
        float i  = sigf(s1 + gxv[1]);
        float o  = sigf(s2 + gxv[2]);
        float cc = tanh_acc(s3 + gxv[3]);
        c_state  = f * c_state + i * cc;
        float h  = o * tanh_acc(c_state);

        g_h[wbuf][(size_t)(b0 + bf) * HID + j] = h;
        __threadfence();
        __syncthreads();   // all h(t) stores done block-wide

        if (tid == 0) {
            __threadfence();
            asm volatile("st.release.gpu.global.u32 [%0], %1;"
                         :: "l"(&g_done[bid]), "r"(base + (unsigned)(t + 1)) : "memory");
        }

        // out stores AFTER release — off the recurrence critical path
        out[((size_t)t * BATCH + b0 + bf) * HID + j] = h;
        if (t == T_LEN - 1) {
            size_t ofs = (size_t)T_LEN * BATCH * HID;
            out[ofs + (size_t)(b0 + bf) * HID + j] = h;
            ofs += (size_t)BATCH * HID;
            out[ofs + (size_t)(b0 + bf) * HID + j] = c_state;
        }
    }
}

// =====================================================================
// launch: fork-join so phase2 (high priority, launched first) overlaps
// with phase1 streaming gx ahead of the recurrence.
// =====================================================================
namespace {
struct LstmStreams {
    cudaStream_t s2 = nullptr;
    cudaEvent_t evF = nullptr, evJ = nullptr;
    LstmStreams() {
        int lo = 0, hi = 0;
        cudaDeviceGetStreamPriorityRange(&lo, &hi);
        cudaStreamCreateWithPriority(&s2, cudaStreamNonBlocking, hi);
        cudaEventCreateWithFlags(&evF, cudaEventDisableTiming);
        cudaEventCreateWithFlags(&evJ, cudaEventDisableTiming);
    }
};
LstmStreams g_ls;   // constructed at static-init, before harness checkpoints
}

extern "C" void kernel_launch(void* const* d_in, const int* in_sizes, int n_in,
                              void* d_out, int out_size) {
    (void)in_sizes; (void)n_in; (void)out_size;
    const float* x  = (const float*)d_in[0];
    const float* Wx = (const float*)d_in[1];
    const float* bx = (const float*)d_in[2];
    const float* Wh = (const float*)d_in[3];
    const float* bh = (const float*)d_in[4];
    float* out = (float*)d_out;

    const int smem1 = (64 * P1_PAD + 32 * P1_PAD) * sizeof(float);   // 50688
    const int smem2 = RED_BYTES + 64 * WS_PAD * sizeof(float);       // 168960
    cudaFuncSetAttribute(lstm_phase1, cudaFuncAttributeMaxDynamicSharedMemorySize, smem1);
    cudaFuncSetAttribute(lstm_phase2, cudaFuncAttributeMaxDynamicSharedMemorySize, smem2);

    // fork: phase2 on high-priority s2 (placed first), phase1 on origin stream
    cudaEventRecord(g_ls.evF, 0);
    cudaStreamWaitEvent(g_ls.s2, g_ls.evF, 0);
    lstm_phase2<<<GRID2, NTHR2, smem2, g_ls.s2>>>(Wh, out);

    dim3 g1(64, T_LEN);
    lstm_phase1<<<g1, 128, smem1>>>(x, Wx, bx, bh);

    // join
    cudaEventRecord(g_ls.evJ, g_ls.s2);
    cudaStreamWaitEvent(0, g_ls.evJ, 0);
}